// round 3
// baseline (speedup 1.0000x reference)
#include <cuda_runtime.h>
#include <math.h>

#define NMAX 100000
#define EMAX 1600000
#define D_IN 512
#define D_H  128
#define D_OUT 40
#define SCAN_B 512

typedef unsigned long long u64;

// ---------------- scratch (static device globals; no dynamic alloc) -------------
__device__ int   g_cnt[NMAX];
__device__ int   g_local[NMAX];
__device__ int   g_partials[512];
__device__ int   g_row_ptr[NMAX + 1];
__device__ int   g_cursor[NMAX];
__device__ int   g_col[EMAX];
__device__ float g_dinv[NMAX];
__device__ float g_h1 [NMAX * D_H];
__device__ float g_h1a[NMAX * D_H];
__device__ float g_h2 [NMAX * D_OUT];

// ---------------- degree / CSR build -------------------------------------------
__global__ void zero_cnt_kernel(int n) {
    int i = blockIdx.x * blockDim.x + threadIdx.x;
    if (i < n) g_cnt[i] = 0;
}

__global__ void count_kernel(const int* __restrict__ dst, int e_cnt) {
    int e = blockIdx.x * blockDim.x + threadIdx.x;
    if (e < e_cnt) atomicAdd(&g_cnt[dst[e]], 1);
}

// block-level exclusive scan of g_cnt -> g_local, block sums -> g_partials
__global__ void scan_block_kernel(int n) {
    __shared__ int sh[SCAN_B];
    int i = blockIdx.x * SCAN_B + threadIdx.x;
    int v = (i < n) ? g_cnt[i] : 0;
    sh[threadIdx.x] = v;
    __syncthreads();
    #pragma unroll
    for (int off = 1; off < SCAN_B; off <<= 1) {
        int t = 0;
        if ((int)threadIdx.x >= off) t = sh[threadIdx.x - off];
        __syncthreads();
        sh[threadIdx.x] += t;
        __syncthreads();
    }
    if (i < n) g_local[i] = sh[threadIdx.x] - v;  // exclusive
    if (threadIdx.x == SCAN_B - 1) g_partials[blockIdx.x] = sh[SCAN_B - 1];
}

// parallel exclusive scan of block sums (nb <= 512), single block
__global__ void scan_partials_kernel(int nb) {
    __shared__ int sh[512];
    int t = threadIdx.x;
    int v = (t < nb) ? g_partials[t] : 0;
    sh[t] = v;
    __syncthreads();
    #pragma unroll
    for (int off = 1; off < 512; off <<= 1) {
        int tv = 0;
        if (t >= off) tv = sh[t - off];
        __syncthreads();
        sh[t] += tv;
        __syncthreads();
    }
    if (t < nb) g_partials[t] = sh[t] - v;  // exclusive
}

// finalize row_ptr, cursor, dinv
__global__ void scan_add_kernel(int n, int e_cnt) {
    int i = blockIdx.x * SCAN_B + threadIdx.x;
    if (i < n) {
        int r = g_local[i] + g_partials[blockIdx.x];
        g_row_ptr[i] = r;
        g_cursor[i]  = r;
        // degree includes the self-loop (+1); always >= 1
        g_dinv[i] = rsqrtf((float)(g_cnt[i] + 1));
    }
    if (i == 0) g_row_ptr[n] = e_cnt;
}

__global__ void fill_csr_kernel(const int* __restrict__ src,
                                const int* __restrict__ dst, int e_cnt) {
    int e = blockIdx.x * blockDim.x + threadIdx.x;
    if (e < e_cnt) {
        int d = dst[e];
        int pos = atomicAdd(&g_cursor[d], 1);
        g_col[pos] = src[e];
    }
}

// ---------------- GEMM1: h1 = x @ W1   (M x 512) @ (512 x 128) ------------------
// BM=64, BN=128, BK=32. 256 threads; per thread 8 rows x 4 cols.
// fp32 packed FFMA2 (fma.rn.f32x2), accumulator paired along K:
//   acc.lo accumulates even k, acc.hi odd k; epilogue sums halves (exact fp32).
// B held K-transposed in smem (stride 34 words: 8B-aligned, phase-conflict-free).
// Thread tn owns cols {tn, tn+32, tn+64, tn+96} (interleaved => conflict-free
// LDS.64 on B and coalesced epilogue stores).
__global__ __launch_bounds__(256, 2) void gemm1_kernel(const float* __restrict__ A,
                                                       const float* __restrict__ B, int M) {
    __shared__ float As[64][32];        // 8 KB  (row-major, k contiguous)
    __shared__ float Bst[128][34];      // 17 KB (n-major, k contiguous, pad 2)
    const int tid = threadIdx.x;
    const int tn = tid & 31;   // col lane
    const int tm = tid >> 5;   // 0..7 -> row group of 8
    const int row0 = blockIdx.x * 64;

    u64 acc[8][4];
    #pragma unroll
    for (int i = 0; i < 8; i++)
        #pragma unroll
        for (int j = 0; j < 4; j++) acc[i][j] = 0ULL;

    for (int k0 = 0; k0 < D_IN; k0 += 32) {
        #pragma unroll
        for (int i = 0; i < 8; i++) {
            int idx = tid + i * 256;
            int m = idx >> 5, k = idx & 31;
            int r = row0 + m;
            As[m][k] = (r < M) ? A[r * D_IN + k0 + k] : 0.f;
        }
        #pragma unroll
        for (int i = 0; i < 16; i++) {
            int idx = tid + i * 256;
            int k = idx >> 7, nn = idx & 127;
            Bst[nn][k] = B[(k0 + k) * D_H + nn];
        }
        __syncthreads();
        #pragma unroll
        for (int kp = 0; kp < 16; kp++) {
            u64 bp[4];
            #pragma unroll
            for (int j = 0; j < 4; j++)
                bp[j] = *(const u64*)&Bst[tn + 32 * j][2 * kp];
            #pragma unroll
            for (int i = 0; i < 8; i++) {
                u64 ap = *(const u64*)&As[tm * 8 + i][2 * kp];
                #pragma unroll
                for (int j = 0; j < 4; j++)
                    asm("fma.rn.f32x2 %0, %1, %2, %0;"
                        : "+l"(acc[i][j]) : "l"(ap), "l"(bp[j]));
            }
        }
        __syncthreads();
    }
    #pragma unroll
    for (int i = 0; i < 8; i++) {
        int r = row0 + tm * 8 + i;
        if (r < M) {
            #pragma unroll
            for (int j = 0; j < 4; j++) {
                float2 v = *reinterpret_cast<float2*>(&acc[i][j]);
                g_h1[r * D_H + tn + 32 * j] = v.x + v.y;
            }
        }
    }
}

// ---------------- Aggregation layer 1: warp per node, 128 cols -----------------
__global__ void agg1_kernel(const float* __restrict__ b1, int n) {
    int warp = (blockIdx.x * blockDim.x + threadIdx.x) >> 5;
    int lane = threadIdx.x & 31;
    if (warp >= n) return;
    const int node = warp;
    const int start = g_row_ptr[node];
    const int end   = g_row_ptr[node + 1];

    float4 acc = make_float4(0.f, 0.f, 0.f, 0.f);
    for (int e = start; e < end; e++) {
        int s = g_col[e];
        float ns = g_dinv[s];
        float4 v = *(const float4*)&g_h1[s * D_H + (lane << 2)];
        acc.x = fmaf(ns, v.x, acc.x);
        acc.y = fmaf(ns, v.y, acc.y);
        acc.z = fmaf(ns, v.z, acc.z);
        acc.w = fmaf(ns, v.w, acc.w);
    }
    float di = g_dinv[node];
    float4 sv = *(const float4*)&g_h1[node * D_H + (lane << 2)];
    float4 bb = *(const float4*)&b1[lane << 2];
    // out = di * (acc + di*self) + b, then ReLU
    float4 o;
    o.x = fmaxf(fmaf(di, fmaf(di, sv.x, acc.x), bb.x), 0.f);
    o.y = fmaxf(fmaf(di, fmaf(di, sv.y, acc.y), bb.y), 0.f);
    o.z = fmaxf(fmaf(di, fmaf(di, sv.z, acc.z), bb.z), 0.f);
    o.w = fmaxf(fmaf(di, fmaf(di, sv.w, acc.w), bb.w), 0.f);
    *(float4*)&g_h1a[node * D_H + (lane << 2)] = o;
}

// ---------------- GEMM2: h2 = h1a @ W2   (M x 128) @ (128 x 40) ----------------
// 32 nodes per block, 256 threads = 32 nodes x 8 groups of 5 cols.
__global__ __launch_bounds__(256) void gemm2_kernel(const float* __restrict__ W2, int M) {
    __shared__ float Ws[D_H * D_OUT];   // 20 KB
    __shared__ float Hs[D_H][33];       // k-major, padded
    const int tid = threadIdx.x;
    const int row0 = blockIdx.x * 32;

    for (int i = tid; i < D_H * D_OUT; i += 256) Ws[i] = W2[i];
    for (int i = tid; i < 32 * D_H; i += 256) {
        int nn = i >> 7, k = i & 127;
        float v = (row0 + nn < M) ? g_h1a[(row0 + nn) * D_H + k] : 0.f;
        Hs[k][nn] = v;
    }
    __syncthreads();

    const int nn = tid & 31;   // node in tile
    const int g  = tid >> 5;   // 0..7 -> 5-col group
    float acc[5];
    #pragma unroll
    for (int j = 0; j < 5; j++) acc[j] = 0.f;

    #pragma unroll 8
    for (int k = 0; k < D_H; k++) {
        float h = Hs[k][nn];
        const float* w = &Ws[k * D_OUT + g * 5];
        #pragma unroll
        for (int j = 0; j < 5; j++) acc[j] = fmaf(h, w[j], acc[j]);
    }
    if (row0 + nn < M) {
        float* op = &g_h2[(row0 + nn) * D_OUT + g * 5];
        #pragma unroll
        for (int j = 0; j < 5; j++) op[j] = acc[j];
    }
}

// ---------------- Aggregation layer 2 + bias + log_softmax ---------------------
__global__ void agg2_kernel(const float* __restrict__ b2, float* __restrict__ out, int n) {
    int warp = (blockIdx.x * blockDim.x + threadIdx.x) >> 5;
    int lane = threadIdx.x & 31;
    if (warp >= n) return;
    const int node = warp;
    const int start = g_row_ptr[node];
    const int end   = g_row_ptr[node + 1];
    const bool hi = (lane < 8);

    float acc0 = 0.f, acc1 = 0.f;
    for (int e = start; e < end; e++) {
        int s = g_col[e];
        float ns = g_dinv[s];
        const float* hp = &g_h2[s * D_OUT];
        acc0 = fmaf(ns, hp[lane], acc0);
        if (hi) acc1 = fmaf(ns, hp[lane + 32], acc1);
    }
    float di = g_dinv[node];
    const float* sp = &g_h2[node * D_OUT];
    float v0 = fmaf(di, fmaf(di, sp[lane], acc0), b2[lane]);
    float v1 = 0.f;
    if (hi) v1 = fmaf(di, fmaf(di, sp[lane + 32], acc1), b2[lane + 32]);

    // warp log_softmax over the 40 values
    float m = hi ? fmaxf(v0, v1) : v0;
    #pragma unroll
    for (int o = 16; o >= 1; o >>= 1)
        m = fmaxf(m, __shfl_xor_sync(0xffffffffu, m, o));
    float s = expf(v0 - m) + (hi ? expf(v1 - m) : 0.f);
    #pragma unroll
    for (int o = 16; o >= 1; o >>= 1)
        s += __shfl_xor_sync(0xffffffffu, s, o);
    float ls = logf(s);

    out[node * D_OUT + lane] = v0 - m - ls;
    if (hi) out[node * D_OUT + 32 + lane] = v1 - m - ls;
}

// ---------------- launch --------------------------------------------------------
extern "C" void kernel_launch(void* const* d_in, const int* in_sizes, int n_in,
                              void* d_out, int out_size) {
    const float* x   = (const float*)d_in[0];
    const int*   ei  = (const int*)d_in[1];    // edge_index is int32 (JAX x64 disabled)
    const float* W1  = (const float*)d_in[2];
    const float* b1  = (const float*)d_in[3];
    const float* W2  = (const float*)d_in[4];
    const float* b2  = (const float*)d_in[5];
    float* out = (float*)d_out;

    const int n = in_sizes[0] / D_IN;   // 100000
    const int e = in_sizes[1] / 2;      // 1600000
    const int* src = ei;
    const int* dst = ei + e;

    const int nb_scan = (n + SCAN_B - 1) / SCAN_B;

    zero_cnt_kernel<<<(n + 255) / 256, 256>>>(n);
    count_kernel<<<(e + 255) / 256, 256>>>(dst, e);
    scan_block_kernel<<<nb_scan, SCAN_B>>>(n);
    scan_partials_kernel<<<1, 512>>>(nb_scan);
    scan_add_kernel<<<nb_scan, SCAN_B>>>(n, e);
    fill_csr_kernel<<<(e + 255) / 256, 256>>>(src, dst, e);

    gemm1_kernel<<<(n + 63) / 64, 256>>>(x, W1, n);
    agg1_kernel<<<(n * 32 + 255) / 256, 256>>>(b1, n);
    gemm2_kernel<<<(n + 31) / 32, 256>>>(W2, n);
    agg2_kernel<<<(n * 32 + 255) / 256, 256>>>(b2, out, n);
}

// round 5
// speedup vs baseline: 1.5929x; 1.5929x over previous
#include <cuda_runtime.h>
#include <cuda_bf16.h>
#include <math.h>
#include <stdint.h>

#define NMAX 100000
#define EMAX 1600000
#define D_IN 512
#define D_H  128
#define D_OUT 40
#define SCAN_B 512

// ================= scratch (static device globals; no dynamic alloc) ===========
__device__ int      g_cnt[NMAX];
__device__ int      g_local[NMAX];
__device__ int      g_partials[512];
__device__ int      g_row_ptr[NMAX + 1];
__device__ int      g_cursor[NMAX];
__device__ int      g_col[EMAX];
__device__ float    g_dinv[NMAX];
__device__ float    g_h1 [NMAX * D_H];
__device__ float    g_h1a[NMAX * D_H];
__device__ float    g_h2 [NMAX * D_OUT];
// W1 split into bf16 hi/lo, [k=512][n=128] row-major (bit patterns as ushort)
__device__ uint16_t g_w1h[D_IN * D_H];
__device__ uint16_t g_w1l[D_IN * D_H];

// ================= small helpers ================================================
__device__ __forceinline__ uint32_t smem_u32(const void* p) {
    uint32_t a;
    asm("{ .reg .u64 t; cvta.to.shared.u64 t, %1; cvt.u32.u64 %0, t; }" : "=r"(a) : "l"(p));
    return a;
}

__device__ __forceinline__ uint16_t bf16_bits(float v) {
    __nv_bfloat16 h = __float2bfloat16(v);
    return *reinterpret_cast<uint16_t*>(&h);
}
__device__ __forceinline__ float bf16_val(uint16_t b) {
    __nv_bfloat16 h = *reinterpret_cast<__nv_bfloat16*>(&b);
    return __bfloat162float(h);
}

// ldmatrix x4 (A, row-major 16x16 bf16 tile)
__device__ __forceinline__ void ldmA(uint32_t* d, const uint16_t* sm, int m0, int kk, int lane) {
    uint32_t addr = smem_u32(sm + (m0 + (lane & 15)) * 40 + kk + ((lane >> 4) << 3));
    asm volatile("ldmatrix.sync.aligned.m8n8.x4.shared.b16 {%0,%1,%2,%3}, [%4];"
                 : "=r"(d[0]), "=r"(d[1]), "=r"(d[2]), "=r"(d[3]) : "r"(addr) : "memory");
}

// ldmatrix x4 trans (B, [k][n] row-major; yields col-major frags for 2 n8-tiles)
__device__ __forceinline__ void ldmB(uint32_t* d, const uint16_t* sm, int kk, int n0, int lane) {
    uint32_t addr = smem_u32(sm + (kk + (lane & 15)) * 136 + n0 + ((lane >> 4) << 3));
    asm volatile("ldmatrix.sync.aligned.m8n8.x4.trans.shared.b16 {%0,%1,%2,%3}, [%4];"
                 : "=r"(d[0]), "=r"(d[1]), "=r"(d[2]), "=r"(d[3]) : "r"(addr) : "memory");
}

__device__ __forceinline__ void mma_bf16(float* c, const uint32_t* a, const uint32_t* b) {
    asm volatile("mma.sync.aligned.m16n8k16.row.col.f32.bf16.bf16.f32 "
                 "{%0,%1,%2,%3}, {%4,%5,%6,%7}, {%8,%9}, {%0,%1,%2,%3};"
                 : "+f"(c[0]), "+f"(c[1]), "+f"(c[2]), "+f"(c[3])
                 : "r"(a[0]), "r"(a[1]), "r"(a[2]), "r"(a[3]), "r"(b[0]), "r"(b[1]));
}

// ---------------- degree / CSR build -------------------------------------------
__global__ void zero_cnt_kernel(int n) {
    int i = blockIdx.x * blockDim.x + threadIdx.x;
    if (i < n) g_cnt[i] = 0;
}

__global__ void count_kernel(const int* __restrict__ dst, int e_cnt) {
    int e = blockIdx.x * blockDim.x + threadIdx.x;
    if (e < e_cnt) atomicAdd(&g_cnt[dst[e]], 1);
}

__global__ void scan_block_kernel(int n) {
    __shared__ int sh[SCAN_B];
    int i = blockIdx.x * SCAN_B + threadIdx.x;
    int v = (i < n) ? g_cnt[i] : 0;
    sh[threadIdx.x] = v;
    __syncthreads();
    #pragma unroll
    for (int off = 1; off < SCAN_B; off <<= 1) {
        int t = 0;
        if ((int)threadIdx.x >= off) t = sh[threadIdx.x - off];
        __syncthreads();
        sh[threadIdx.x] += t;
        __syncthreads();
    }
    if (i < n) g_local[i] = sh[threadIdx.x] - v;
    if (threadIdx.x == SCAN_B - 1) g_partials[blockIdx.x] = sh[SCAN_B - 1];
}

__global__ void scan_partials_kernel(int nb) {
    __shared__ int sh[512];
    int t = threadIdx.x;
    int v = (t < nb) ? g_partials[t] : 0;
    sh[t] = v;
    __syncthreads();
    #pragma unroll
    for (int off = 1; off < 512; off <<= 1) {
        int tv = 0;
        if (t >= off) tv = sh[t - off];
        __syncthreads();
        sh[t] += tv;
        __syncthreads();
    }
    if (t < nb) g_partials[t] = sh[t] - v;
}

__global__ void scan_add_kernel(int n, int e_cnt) {
    int i = blockIdx.x * SCAN_B + threadIdx.x;
    if (i < n) {
        int r = g_local[i] + g_partials[blockIdx.x];
        g_row_ptr[i] = r;
        g_cursor[i]  = r;
        g_dinv[i] = rsqrtf((float)(g_cnt[i] + 1));
    }
    if (i == 0) g_row_ptr[n] = e_cnt;
}

__global__ void fill_csr_kernel(const int* __restrict__ src,
                                const int* __restrict__ dst, int e_cnt) {
    int e = blockIdx.x * blockDim.x + threadIdx.x;
    if (e < e_cnt) {
        int d = dst[e];
        int pos = atomicAdd(&g_cursor[d], 1);
        g_col[pos] = src[e];
    }
}

// ---------------- W1 prep: fp32 [k][n] -> split bf16 hi/lo [k][n] ---------------
__global__ void w1_prep_kernel(const float* __restrict__ W1) {
    int i = blockIdx.x * blockDim.x + threadIdx.x;
    if (i >= D_IN * D_H) return;
    float v = W1[i];
    uint16_t h = bf16_bits(v);
    g_w1h[i] = h;
    g_w1l[i] = bf16_bits(v - bf16_val(h));
}

// ---------------- GEMM1 (HMMA): h1 = x @ W1  (M x 512) @ (512 x 128) -----------
// Block 128x128, 256 threads = 8 warps (4m x 2n), warp tile 32x64, BK=32.
// Split-bf16: hi*Whi + hi*Wlo + lo*Whi.
__global__ __launch_bounds__(256) void gemm1_mma_kernel(const float* __restrict__ A, int M) {
    __shared__ __align__(16) uint16_t As_hi[128 * 40];  // row stride 40 bf16 (80B)
    __shared__ __align__(16) uint16_t As_lo[128 * 40];
    __shared__ __align__(16) uint16_t Bs_hi[32 * 136];  // [k][n], stride 136 (272B)
    __shared__ __align__(16) uint16_t Bs_lo[32 * 136];

    const int tid  = threadIdx.x;
    const int lane = tid & 31;
    const int wid  = tid >> 5;
    const int wm   = wid >> 1;      // 0..3 (m group of 32 rows)
    const int wn   = wid & 1;       // 0..1 (n group of 64 cols)
    const int row0 = blockIdx.x * 128;

    float acc[2][8][4];
    #pragma unroll
    for (int a = 0; a < 2; a++)
        #pragma unroll
        for (int b = 0; b < 8; b++)
            #pragma unroll
            for (int c = 0; c < 4; c++) acc[a][b][c] = 0.f;

    uint32_t* Ah32 = reinterpret_cast<uint32_t*>(As_hi);
    uint32_t* Al32 = reinterpret_cast<uint32_t*>(As_lo);

    for (int ch = 0; ch < 16; ch++) {
        const int k0 = ch * 32;
        // ---- A chunk: 128 rows x 32 k fp32 -> bf16 hi/lo into smem ----
        #pragma unroll
        for (int i = 0; i < 4; i++) {
            int idx = tid + i * 256;           // 1024 float4 slots
            int m  = idx >> 3;
            int kq = idx & 7;                  // float4 within row (k = kq*4)
            int r  = row0 + m;
            float4 v = make_float4(0.f, 0.f, 0.f, 0.f);
            if (r < M) v = *(const float4*)&A[(size_t)r * D_IN + k0 + kq * 4];
            uint16_t h0 = bf16_bits(v.x), h1 = bf16_bits(v.y),
                     h2 = bf16_bits(v.z), h3 = bf16_bits(v.w);
            uint16_t l0 = bf16_bits(v.x - bf16_val(h0)), l1 = bf16_bits(v.y - bf16_val(h1)),
                     l2 = bf16_bits(v.z - bf16_val(h2)), l3 = bf16_bits(v.w - bf16_val(h3));
            int w = m * 20 + kq * 2;           // uint32 index (row stride 40 bf16 = 20 u32)
            Ah32[w]     = (uint32_t)h0 | ((uint32_t)h1 << 16);
            Ah32[w + 1] = (uint32_t)h2 | ((uint32_t)h3 << 16);
            Al32[w]     = (uint32_t)l0 | ((uint32_t)l1 << 16);
            Al32[w + 1] = (uint32_t)l2 | ((uint32_t)l3 << 16);
        }
        // ---- B chunk: 32 k x 128 n bf16 hi/lo copy (uint4 = 8 bf16) ----
        #pragma unroll
        for (int i = 0; i < 2; i++) {
            int idx = tid + i * 256;           // 512 uint4 slots
            int k = idx >> 4;
            int u = idx & 15;                  // 8-bf16 group
            const uint4* sh = (const uint4*)&g_w1h[(size_t)(k0 + k) * D_H + u * 8];
            const uint4* sl = (const uint4*)&g_w1l[(size_t)(k0 + k) * D_H + u * 8];
            *(uint4*)&Bs_hi[k * 136 + u * 8] = *sh;
            *(uint4*)&Bs_lo[k * 136 + u * 8] = *sl;
        }
        __syncthreads();

        #pragma unroll
        for (int kk = 0; kk < 32; kk += 16) {
            uint32_t ah[2][4], al[2][4];
            #pragma unroll
            for (int mt = 0; mt < 2; mt++) {
                ldmA(ah[mt], As_hi, wm * 32 + mt * 16, kk, lane);
                ldmA(al[mt], As_lo, wm * 32 + mt * 16, kk, lane);
            }
            #pragma unroll
            for (int ng = 0; ng < 4; ng++) {   // pairs of n8 tiles
                uint32_t bh[4], bl[4];
                ldmB(bh, Bs_hi, kk, wn * 64 + ng * 16, lane);
                ldmB(bl, Bs_lo, kk, wn * 64 + ng * 16, lane);
                #pragma unroll
                for (int mt = 0; mt < 2; mt++) {
                    mma_bf16(acc[mt][ng * 2],     ah[mt], bh);
                    mma_bf16(acc[mt][ng * 2],     ah[mt], bl);
                    mma_bf16(acc[mt][ng * 2],     al[mt], bh);
                    mma_bf16(acc[mt][ng * 2 + 1], ah[mt], bh + 2);
                    mma_bf16(acc[mt][ng * 2 + 1], ah[mt], bl + 2);
                    mma_bf16(acc[mt][ng * 2 + 1], al[mt], bh + 2);
                }
            }
        }
        __syncthreads();
    }

    // ---- epilogue: c0,c1 -> (row g, col 2t..2t+1); c2,c3 -> (row g+8) ----
    const int g   = lane >> 2;
    const int tg  = lane & 3;
    #pragma unroll
    for (int mt = 0; mt < 2; mt++) {
        #pragma unroll
        for (int nt = 0; nt < 8; nt++) {
            int col = wn * 64 + nt * 8 + tg * 2;
            int r0  = row0 + wm * 32 + mt * 16 + g;
            if (r0 < M)
                *(float2*)&g_h1[(size_t)r0 * D_H + col] =
                    make_float2(acc[mt][nt][0], acc[mt][nt][1]);
            int r1 = r0 + 8;
            if (r1 < M)
                *(float2*)&g_h1[(size_t)r1 * D_H + col] =
                    make_float2(acc[mt][nt][2], acc[mt][nt][3]);
        }
    }
}

// ---------------- Aggregation layer 1: warp per node, 128 cols -----------------
__global__ void agg1_kernel(const float* __restrict__ b1, int n) {
    int warp = (blockIdx.x * blockDim.x + threadIdx.x) >> 5;
    int lane = threadIdx.x & 31;
    if (warp >= n) return;
    const int node = warp;
    const int start = g_row_ptr[node];
    const int end   = g_row_ptr[node + 1];

    float4 acc = make_float4(0.f, 0.f, 0.f, 0.f);
    for (int e = start; e < end; e++) {
        int s = g_col[e];
        float ns = g_dinv[s];
        float4 v = *(const float4*)&g_h1[(size_t)s * D_H + (lane << 2)];
        acc.x = fmaf(ns, v.x, acc.x);
        acc.y = fmaf(ns, v.y, acc.y);
        acc.z = fmaf(ns, v.z, acc.z);
        acc.w = fmaf(ns, v.w, acc.w);
    }
    float di = g_dinv[node];
    float4 sv = *(const float4*)&g_h1[(size_t)node * D_H + (lane << 2)];
    float4 bb = *(const float4*)&b1[lane << 2];
    float4 o;
    o.x = fmaxf(fmaf(di, fmaf(di, sv.x, acc.x), bb.x), 0.f);
    o.y = fmaxf(fmaf(di, fmaf(di, sv.y, acc.y), bb.y), 0.f);
    o.z = fmaxf(fmaf(di, fmaf(di, sv.z, acc.z), bb.z), 0.f);
    o.w = fmaxf(fmaf(di, fmaf(di, sv.w, acc.w), bb.w), 0.f);
    *(float4*)&g_h1a[(size_t)node * D_H + (lane << 2)] = o;
}

// ---------------- GEMM2: h2 = h1a @ W2   (M x 128) @ (128 x 40) ----------------
__global__ __launch_bounds__(256) void gemm2_kernel(const float* __restrict__ W2, int M) {
    __shared__ float Ws[D_H * D_OUT];
    __shared__ float Hs[D_H][33];
    const int tid = threadIdx.x;
    const int row0 = blockIdx.x * 32;

    for (int i = tid; i < D_H * D_OUT; i += 256) Ws[i] = W2[i];
    for (int i = tid; i < 32 * D_H; i += 256) {
        int nn = i >> 7, k = i & 127;
        float v = (row0 + nn < M) ? g_h1a[(size_t)(row0 + nn) * D_H + k] : 0.f;
        Hs[k][nn] = v;
    }
    __syncthreads();

    const int nn = tid & 31;
    const int g  = tid >> 5;
    float acc[5];
    #pragma unroll
    for (int j = 0; j < 5; j++) acc[j] = 0.f;

    #pragma unroll 8
    for (int k = 0; k < D_H; k++) {
        float h = Hs[k][nn];
        const float* w = &Ws[k * D_OUT + g * 5];
        #pragma unroll
        for (int j = 0; j < 5; j++) acc[j] = fmaf(h, w[j], acc[j]);
    }
    if (row0 + nn < M) {
        float* op = &g_h2[(size_t)(row0 + nn) * D_OUT + g * 5];
        #pragma unroll
        for (int j = 0; j < 5; j++) op[j] = acc[j];
    }
}

// ---------------- Aggregation layer 2 + bias + log_softmax ---------------------
__global__ void agg2_kernel(const float* __restrict__ b2, float* __restrict__ out, int n) {
    int warp = (blockIdx.x * blockDim.x + threadIdx.x) >> 5;
    int lane = threadIdx.x & 31;
    if (warp >= n) return;
    const int node = warp;
    const int start = g_row_ptr[node];
    const int end   = g_row_ptr[node + 1];
    const bool hi = (lane < 8);

    float acc0 = 0.f, acc1 = 0.f;
    for (int e = start; e < end; e++) {
        int s = g_col[e];
        float ns = g_dinv[s];
        const float* hp = &g_h2[(size_t)s * D_OUT];
        acc0 = fmaf(ns, hp[lane], acc0);
        if (hi) acc1 = fmaf(ns, hp[lane + 32], acc1);
    }
    float di = g_dinv[node];
    const float* sp = &g_h2[(size_t)node * D_OUT];
    float v0 = fmaf(di, fmaf(di, sp[lane], acc0), b2[lane]);
    float v1 = 0.f;
    if (hi) v1 = fmaf(di, fmaf(di, sp[lane + 32], acc1), b2[lane + 32]);

    float m = hi ? fmaxf(v0, v1) : v0;
    #pragma unroll
    for (int o = 16; o >= 1; o >>= 1)
        m = fmaxf(m, __shfl_xor_sync(0xffffffffu, m, o));
    float s = expf(v0 - m) + (hi ? expf(v1 - m) : 0.f);
    #pragma unroll
    for (int o = 16; o >= 1; o >>= 1)
        s += __shfl_xor_sync(0xffffffffu, s, o);
    float ls = logf(s);

    out[node * D_OUT + lane] = v0 - m - ls;
    if (hi) out[node * D_OUT + 32 + lane] = v1 - m - ls;
}

// ---------------- launch --------------------------------------------------------
extern "C" void kernel_launch(void* const* d_in, const int* in_sizes, int n_in,
                              void* d_out, int out_size) {
    const float* x   = (const float*)d_in[0];
    const int*   ei  = (const int*)d_in[1];    // edge_index is int32 (JAX x64 disabled)
    const float* W1  = (const float*)d_in[2];
    const float* b1  = (const float*)d_in[3];
    const float* W2  = (const float*)d_in[4];
    const float* b2  = (const float*)d_in[5];
    float* out = (float*)d_out;

    const int n = in_sizes[0] / D_IN;   // 100000
    const int e = in_sizes[1] / 2;      // 1600000
    const int* src = ei;
    const int* dst = ei + e;

    const int nb_scan = (n + SCAN_B - 1) / SCAN_B;

    zero_cnt_kernel<<<(n + 255) / 256, 256>>>(n);
    count_kernel<<<(e + 255) / 256, 256>>>(dst, e);
    scan_block_kernel<<<nb_scan, SCAN_B>>>(n);
    scan_partials_kernel<<<1, 512>>>(nb_scan);
    scan_add_kernel<<<nb_scan, SCAN_B>>>(n, e);
    fill_csr_kernel<<<(e + 255) / 256, 256>>>(src, dst, e);

    w1_prep_kernel<<<(D_IN * D_H + 255) / 256, 256>>>(W1);
    gemm1_mma_kernel<<<(n + 127) / 128, 256>>>(x, n);
    agg1_kernel<<<(n * 32 + 255) / 256, 256>>>(b1, n);
    gemm2_kernel<<<(n + 31) / 32, 256>>>(W2, n);
    agg2_kernel<<<(n * 32 + 255) / 256, 256>>>(b2, out, n);
}

// round 6
// speedup vs baseline: 1.9462x; 1.2218x over previous
#include <cuda_runtime.h>
#include <cuda_bf16.h>
#include <math.h>
#include <stdint.h>

#define NMAX 100000
#define EMAX 1600000
#define D_IN 512
#define D_H  128
#define D_OUT 40
#define SCAN_B 512

// ================= scratch (static device globals; no dynamic alloc) ===========
__device__ int      g_cnt[NMAX];
__device__ int      g_local[NMAX];
__device__ int      g_partials[512];
__device__ int      g_row_ptr[NMAX + 1];
__device__ int      g_cursor[NMAX];
__device__ int      g_col[EMAX];
__device__ float    g_dinv[NMAX];
__device__ float    g_h1 [NMAX * D_H];
__device__ float    g_h2 [NMAX * D_OUT];
// h1a (post agg+relu) stored pre-split as bf16 hi/lo, packed 2 per u32, row = 64 u32
__device__ uint32_t g_h1h[NMAX * 64];
__device__ uint32_t g_h1l[NMAX * 64];
// W1 split into bf16 hi/lo, [k=512][n=128] row-major (bit patterns as ushort)
__device__ uint16_t g_w1h[D_IN * D_H];
__device__ uint16_t g_w1l[D_IN * D_H];
// W2 split into bf16 hi/lo, [k=128][n=56 padded] stored as u32 words [128][28]
__device__ uint32_t g_w2h[128 * 28];
__device__ uint32_t g_w2l[128 * 28];

// ================= small helpers ================================================
__device__ __forceinline__ uint32_t smem_u32(const void* p) {
    uint32_t a;
    asm("{ .reg .u64 t; cvta.to.shared.u64 t, %1; cvt.u32.u64 %0, t; }" : "=r"(a) : "l"(p));
    return a;
}

__device__ __forceinline__ uint16_t bf16_bits(float v) {
    __nv_bfloat16 h = __float2bfloat16(v);
    return *reinterpret_cast<uint16_t*>(&h);
}
__device__ __forceinline__ float bf16_val(uint16_t b) {
    __nv_bfloat16 h = *reinterpret_cast<__nv_bfloat16*>(&b);
    return __bfloat162float(h);
}

// ldmatrix x4 (A, row-major 16x16 bf16 tile, row stride 40 bf16)
__device__ __forceinline__ void ldmA(uint32_t* d, const uint16_t* sm, int m0, int kk, int lane) {
    uint32_t addr = smem_u32(sm + (m0 + (lane & 15)) * 40 + kk + ((lane >> 4) << 3));
    asm volatile("ldmatrix.sync.aligned.m8n8.x4.shared.b16 {%0,%1,%2,%3}, [%4];"
                 : "=r"(d[0]), "=r"(d[1]), "=r"(d[2]), "=r"(d[3]) : "r"(addr) : "memory");
}

// ldmatrix x4 trans (B, [k][n] row-major stride 136; two n8 tiles)
__device__ __forceinline__ void ldmB(uint32_t* d, const uint16_t* sm, int kk, int n0, int lane) {
    uint32_t addr = smem_u32(sm + (kk + (lane & 15)) * 136 + n0 + ((lane >> 4) << 3));
    asm volatile("ldmatrix.sync.aligned.m8n8.x4.trans.shared.b16 {%0,%1,%2,%3}, [%4];"
                 : "=r"(d[0]), "=r"(d[1]), "=r"(d[2]), "=r"(d[3]) : "r"(addr) : "memory");
}

// ldmatrix x2 trans (B, [k][n] row-major stride 56; one n8 tile, k16)
__device__ __forceinline__ void ldmB2(uint32_t* d, const uint16_t* sm, int kk, int n0, int lane) {
    uint32_t addr = smem_u32(sm + (kk + (lane & 15)) * 56 + n0);
    asm volatile("ldmatrix.sync.aligned.m8n8.x2.trans.shared.b16 {%0,%1}, [%2];"
                 : "=r"(d[0]), "=r"(d[1]) : "r"(addr) : "memory");
}

__device__ __forceinline__ void mma_bf16(float* c, const uint32_t* a, const uint32_t* b) {
    asm volatile("mma.sync.aligned.m16n8k16.row.col.f32.bf16.bf16.f32 "
                 "{%0,%1,%2,%3}, {%4,%5,%6,%7}, {%8,%9}, {%0,%1,%2,%3};"
                 : "+f"(c[0]), "+f"(c[1]), "+f"(c[2]), "+f"(c[3])
                 : "r"(a[0]), "r"(a[1]), "r"(a[2]), "r"(a[3]), "r"(b[0]), "r"(b[1]));
}

// ---------------- degree / CSR build -------------------------------------------
__global__ void zero_cnt_kernel(int n) {
    int i = blockIdx.x * blockDim.x + threadIdx.x;
    if (i < n) g_cnt[i] = 0;
}

__global__ void count_kernel(const int* __restrict__ dst, int e_cnt) {
    int e = blockIdx.x * blockDim.x + threadIdx.x;
    if (e < e_cnt) atomicAdd(&g_cnt[dst[e]], 1);
}

__global__ void scan_block_kernel(int n) {
    __shared__ int sh[SCAN_B];
    int i = blockIdx.x * SCAN_B + threadIdx.x;
    int v = (i < n) ? g_cnt[i] : 0;
    sh[threadIdx.x] = v;
    __syncthreads();
    #pragma unroll
    for (int off = 1; off < SCAN_B; off <<= 1) {
        int t = 0;
        if ((int)threadIdx.x >= off) t = sh[threadIdx.x - off];
        __syncthreads();
        sh[threadIdx.x] += t;
        __syncthreads();
    }
    if (i < n) g_local[i] = sh[threadIdx.x] - v;
    if (threadIdx.x == SCAN_B - 1) g_partials[blockIdx.x] = sh[SCAN_B - 1];
}

__global__ void scan_partials_kernel(int nb) {
    __shared__ int sh[512];
    int t = threadIdx.x;
    int v = (t < nb) ? g_partials[t] : 0;
    sh[t] = v;
    __syncthreads();
    #pragma unroll
    for (int off = 1; off < 512; off <<= 1) {
        int tv = 0;
        if (t >= off) tv = sh[t - off];
        __syncthreads();
        sh[t] += tv;
        __syncthreads();
    }
    if (t < nb) g_partials[t] = sh[t] - v;
}

__global__ void scan_add_kernel(int n, int e_cnt) {
    int i = blockIdx.x * SCAN_B + threadIdx.x;
    if (i < n) {
        int r = g_local[i] + g_partials[blockIdx.x];
        g_row_ptr[i] = r;
        g_cursor[i]  = r;
        g_dinv[i] = rsqrtf((float)(g_cnt[i] + 1));
    }
    if (i == 0) g_row_ptr[n] = e_cnt;
}

__global__ void fill_csr_kernel(const int* __restrict__ src,
                                const int* __restrict__ dst, int e_cnt) {
    int e = blockIdx.x * blockDim.x + threadIdx.x;
    if (e < e_cnt) {
        int d = dst[e];
        int pos = atomicAdd(&g_cursor[d], 1);
        g_col[pos] = src[e];
    }
}

// ---------------- weight prep ----------------------------------------------------
__global__ void w1_prep_kernel(const float* __restrict__ W1) {
    int i = blockIdx.x * blockDim.x + threadIdx.x;
    if (i >= D_IN * D_H) return;
    float v = W1[i];
    uint16_t h = bf16_bits(v);
    g_w1h[i] = h;
    g_w1l[i] = bf16_bits(v - bf16_val(h));
}

// W2 [128][40] fp32 -> padded [128][56] bf16 hi/lo as u32 words [128][28]
__global__ void w2_prep_kernel(const float* __restrict__ W2) {
    int i = blockIdx.x * blockDim.x + threadIdx.x;   // 128*28 = 3584 words
    if (i >= 128 * 28) return;
    int k = i / 28;
    int j = i % 28;       // bf16 pair index: cols 2j, 2j+1
    float v0 = (2 * j     < D_OUT) ? W2[k * D_OUT + 2 * j]     : 0.f;
    float v1 = (2 * j + 1 < D_OUT) ? W2[k * D_OUT + 2 * j + 1] : 0.f;
    uint16_t h0 = bf16_bits(v0), h1 = bf16_bits(v1);
    uint16_t l0 = bf16_bits(v0 - bf16_val(h0)), l1 = bf16_bits(v1 - bf16_val(h1));
    g_w2h[i] = (uint32_t)h0 | ((uint32_t)h1 << 16);
    g_w2l[i] = (uint32_t)l0 | ((uint32_t)l1 << 16);
}

// ---------------- GEMM1 (HMMA): h1 = x @ W1  (M x 512) @ (512 x 128) -----------
// Block 128x128, 256 threads = 8 warps (4m x 2n), warp tile 32x64, BK=32.
// Split-bf16: hi*Whi + hi*Wlo + lo*Whi. A-prefetch pipelined across chunks.
__global__ __launch_bounds__(256, 2) void gemm1_mma_kernel(const float* __restrict__ A, int M) {
    __shared__ __align__(16) uint16_t As_hi[128 * 40];
    __shared__ __align__(16) uint16_t As_lo[128 * 40];
    __shared__ __align__(16) uint16_t Bs_hi[32 * 136];
    __shared__ __align__(16) uint16_t Bs_lo[32 * 136];

    const int tid  = threadIdx.x;
    const int lane = tid & 31;
    const int wid  = tid >> 5;
    const int wm   = wid >> 1;
    const int wn   = wid & 1;
    const int row0 = blockIdx.x * 128;

    // this thread's A-slot coordinates (4 float4 per chunk)
    int am[4], akq[4];
    bool aok[4];
    #pragma unroll
    for (int i = 0; i < 4; i++) {
        int idx = tid + i * 256;
        am[i]  = idx >> 3;
        akq[i] = idx & 7;
        aok[i] = (row0 + am[i]) < M;
    }

    float acc[2][8][4];
    #pragma unroll
    for (int a = 0; a < 2; a++)
        #pragma unroll
        for (int b = 0; b < 8; b++)
            #pragma unroll
            for (int c = 0; c < 4; c++) acc[a][b][c] = 0.f;

    uint32_t* Ah32 = reinterpret_cast<uint32_t*>(As_hi);
    uint32_t* Al32 = reinterpret_cast<uint32_t*>(As_lo);

    // prefetch chunk 0
    float4 v[4];
    #pragma unroll
    for (int i = 0; i < 4; i++)
        v[i] = aok[i] ? *(const float4*)&A[(size_t)(row0 + am[i]) * D_IN + akq[i] * 4]
                      : make_float4(0.f, 0.f, 0.f, 0.f);

    for (int ch = 0; ch < 16; ch++) {
        // ---- convert prefetched A chunk into smem ----
        #pragma unroll
        for (int i = 0; i < 4; i++) {
            uint16_t h0 = bf16_bits(v[i].x), h1 = bf16_bits(v[i].y),
                     h2 = bf16_bits(v[i].z), h3 = bf16_bits(v[i].w);
            uint16_t l0 = bf16_bits(v[i].x - bf16_val(h0)), l1 = bf16_bits(v[i].y - bf16_val(h1)),
                     l2 = bf16_bits(v[i].z - bf16_val(h2)), l3 = bf16_bits(v[i].w - bf16_val(h3));
            int w = am[i] * 20 + akq[i] * 2;
            Ah32[w]     = (uint32_t)h0 | ((uint32_t)h1 << 16);
            Ah32[w + 1] = (uint32_t)h2 | ((uint32_t)h3 << 16);
            Al32[w]     = (uint32_t)l0 | ((uint32_t)l1 << 16);
            Al32[w + 1] = (uint32_t)l2 | ((uint32_t)l3 << 16);
        }
        // ---- B chunk copy ----
        const int k0 = ch * 32;
        #pragma unroll
        for (int i = 0; i < 2; i++) {
            int idx = tid + i * 256;
            int k = idx >> 4;
            int u = idx & 15;
            *(uint4*)&Bs_hi[k * 136 + u * 8] = *(const uint4*)&g_w1h[(size_t)(k0 + k) * D_H + u * 8];
            *(uint4*)&Bs_lo[k * 136 + u * 8] = *(const uint4*)&g_w1l[(size_t)(k0 + k) * D_H + u * 8];
        }
        __syncthreads();

        // ---- prefetch next A chunk (overlaps MMA below) ----
        if (ch < 15) {
            const int kn = (ch + 1) * 32;
            #pragma unroll
            for (int i = 0; i < 4; i++)
                v[i] = aok[i] ? *(const float4*)&A[(size_t)(row0 + am[i]) * D_IN + kn + akq[i] * 4]
                              : make_float4(0.f, 0.f, 0.f, 0.f);
        }

        #pragma unroll
        for (int kk = 0; kk < 32; kk += 16) {
            uint32_t ah[2][4], al[2][4];
            #pragma unroll
            for (int mt = 0; mt < 2; mt++) {
                ldmA(ah[mt], As_hi, wm * 32 + mt * 16, kk, lane);
                ldmA(al[mt], As_lo, wm * 32 + mt * 16, kk, lane);
            }
            #pragma unroll
            for (int ng = 0; ng < 4; ng++) {
                uint32_t bh[4], bl[4];
                ldmB(bh, Bs_hi, kk, wn * 64 + ng * 16, lane);
                ldmB(bl, Bs_lo, kk, wn * 64 + ng * 16, lane);
                #pragma unroll
                for (int mt = 0; mt < 2; mt++) {
                    mma_bf16(acc[mt][ng * 2],     ah[mt], bh);
                    mma_bf16(acc[mt][ng * 2],     ah[mt], bl);
                    mma_bf16(acc[mt][ng * 2],     al[mt], bh);
                    mma_bf16(acc[mt][ng * 2 + 1], ah[mt], bh + 2);
                    mma_bf16(acc[mt][ng * 2 + 1], ah[mt], bl + 2);
                    mma_bf16(acc[mt][ng * 2 + 1], al[mt], bh + 2);
                }
            }
        }
        __syncthreads();
    }

    const int g  = lane >> 2;
    const int tg = lane & 3;
    #pragma unroll
    for (int mt = 0; mt < 2; mt++) {
        #pragma unroll
        for (int nt = 0; nt < 8; nt++) {
            int col = wn * 64 + nt * 8 + tg * 2;
            int r0  = row0 + wm * 32 + mt * 16 + g;
            if (r0 < M)
                *(float2*)&g_h1[(size_t)r0 * D_H + col] =
                    make_float2(acc[mt][nt][0], acc[mt][nt][1]);
            int r1 = r0 + 8;
            if (r1 < M)
                *(float2*)&g_h1[(size_t)r1 * D_H + col] =
                    make_float2(acc[mt][nt][2], acc[mt][nt][3]);
        }
    }
}

// ---------------- Aggregation layer 1: warp per node, writes split bf16 --------
__global__ void agg1_kernel(const float* __restrict__ b1, int n) {
    int warp = (blockIdx.x * blockDim.x + threadIdx.x) >> 5;
    int lane = threadIdx.x & 31;
    if (warp >= n) return;
    const int node = warp;
    const int start = g_row_ptr[node];
    const int end   = g_row_ptr[node + 1];

    float4 acc = make_float4(0.f, 0.f, 0.f, 0.f);
    for (int e = start; e < end; e++) {
        int s = g_col[e];
        float ns = g_dinv[s];
        float4 v = *(const float4*)&g_h1[(size_t)s * D_H + (lane << 2)];
        acc.x = fmaf(ns, v.x, acc.x);
        acc.y = fmaf(ns, v.y, acc.y);
        acc.z = fmaf(ns, v.z, acc.z);
        acc.w = fmaf(ns, v.w, acc.w);
    }
    float di = g_dinv[node];
    float4 sv = *(const float4*)&g_h1[(size_t)node * D_H + (lane << 2)];
    float4 bb = *(const float4*)&b1[lane << 2];
    float4 o;
    o.x = fmaxf(fmaf(di, fmaf(di, sv.x, acc.x), bb.x), 0.f);
    o.y = fmaxf(fmaf(di, fmaf(di, sv.y, acc.y), bb.y), 0.f);
    o.z = fmaxf(fmaf(di, fmaf(di, sv.z, acc.z), bb.z), 0.f);
    o.w = fmaxf(fmaf(di, fmaf(di, sv.w, acc.w), bb.w), 0.f);

    // split to bf16 hi/lo, pack pairs
    uint16_t h0 = bf16_bits(o.x), h1 = bf16_bits(o.y), h2 = bf16_bits(o.z), h3 = bf16_bits(o.w);
    uint16_t l0 = bf16_bits(o.x - bf16_val(h0)), l1 = bf16_bits(o.y - bf16_val(h1)),
             l2 = bf16_bits(o.z - bf16_val(h2)), l3 = bf16_bits(o.w - bf16_val(h3));
    uint2 hp = make_uint2((uint32_t)h0 | ((uint32_t)h1 << 16), (uint32_t)h2 | ((uint32_t)h3 << 16));
    uint2 lp = make_uint2((uint32_t)l0 | ((uint32_t)l1 << 16), (uint32_t)l2 | ((uint32_t)l3 << 16));
    *(uint2*)&g_h1h[(size_t)node * 64 + lane * 2] = hp;
    *(uint2*)&g_h1l[(size_t)node * 64 + lane * 2] = lp;
}

// ---------------- GEMM2 (HMMA): h2 = h1a @ W2  (M x 128) @ (128 x 40) ----------
// Block 128 rows, 256 threads = 8 warps x 16 rows each. N=40 = 5 n8 tiles.
// K=128 in 4 chunks of 32. Split-bf16 (inputs pre-split).
__global__ __launch_bounds__(256) void gemm2_mma_kernel(int M) {
    __shared__ __align__(16) uint16_t Ah[128 * 40];   // [m][k] stride 40
    __shared__ __align__(16) uint16_t Al[128 * 40];
    __shared__ __align__(16) uint16_t Bh[32 * 56];    // [k][n] stride 56
    __shared__ __align__(16) uint16_t Bl[32 * 56];

    const int tid  = threadIdx.x;
    const int lane = tid & 31;
    const int wid  = tid >> 5;
    const int row0 = blockIdx.x * 128;

    uint32_t* Ah32 = reinterpret_cast<uint32_t*>(Ah);
    uint32_t* Al32 = reinterpret_cast<uint32_t*>(Al);
    uint32_t* Bh32 = reinterpret_cast<uint32_t*>(Bh);
    uint32_t* Bl32 = reinterpret_cast<uint32_t*>(Bl);

    float acc[5][4];
    #pragma unroll
    for (int a = 0; a < 5; a++)
        #pragma unroll
        for (int c = 0; c < 4; c++) acc[a][c] = 0.f;

    for (int ch = 0; ch < 4; ch++) {
        const int kw0 = ch * 16;   // u32 word offset within row (32 bf16 = 16 words)
        // ---- A chunk: 128 rows x 16 u32 words ----
        #pragma unroll
        for (int i = 0; i < 8; i++) {
            int idx = tid + i * 256;      // 2048
            int m = idx >> 4, j = idx & 15;
            int r = row0 + m;
            uint32_t vh = 0, vl = 0;
            if (r < M) {
                vh = g_h1h[(size_t)r * 64 + kw0 + j];
                vl = g_h1l[(size_t)r * 64 + kw0 + j];
            }
            Ah32[m * 20 + j] = vh;
            Al32[m * 20 + j] = vl;
        }
        // ---- B chunk: rows k0..k0+31 of g_w2 (28 u32 per row) ----
        #pragma unroll
        for (int i = 0; i < 4; i++) {
            int idx = tid + i * 256;      // need 896
            if (idx < 896) {
                int k = idx / 28, j = idx % 28;
                Bh32[k * 28 + j] = g_w2h[(ch * 32 + k) * 28 + j];
                Bl32[k * 28 + j] = g_w2l[(ch * 32 + k) * 28 + j];
            }
        }
        __syncthreads();

        #pragma unroll
        for (int kk = 0; kk < 32; kk += 16) {
            uint32_t ah[4], al[4];
            ldmA(ah, Ah, wid * 16, kk, lane);
            ldmA(al, Al, wid * 16, kk, lane);
            #pragma unroll
            for (int nt = 0; nt < 5; nt++) {
                uint32_t bh[2], bl[2];
                ldmB2(bh, Bh, kk, nt * 8, lane);
                ldmB2(bl, Bl, kk, nt * 8, lane);
                mma_bf16(acc[nt], ah, bh);
                mma_bf16(acc[nt], ah, bl);
                mma_bf16(acc[nt], al, bh);
            }
        }
        __syncthreads();
    }

    const int g  = lane >> 2;
    const int tg = lane & 3;
    #pragma unroll
    for (int nt = 0; nt < 5; nt++) {
        int col = nt * 8 + tg * 2;
        int r0  = row0 + wid * 16 + g;
        if (r0 < M)
            *(float2*)&g_h2[(size_t)r0 * D_OUT + col] = make_float2(acc[nt][0], acc[nt][1]);
        int r1 = r0 + 8;
        if (r1 < M)
            *(float2*)&g_h2[(size_t)r1 * D_OUT + col] = make_float2(acc[nt][2], acc[nt][3]);
    }
}

// ---------------- Aggregation layer 2 + bias + log_softmax ---------------------
__global__ void agg2_kernel(const float* __restrict__ b2, float* __restrict__ out, int n) {
    int warp = (blockIdx.x * blockDim.x + threadIdx.x) >> 5;
    int lane = threadIdx.x & 31;
    if (warp >= n) return;
    const int node = warp;
    const int start = g_row_ptr[node];
    const int end   = g_row_ptr[node + 1];
    const bool hi = (lane < 8);

    float acc0 = 0.f, acc1 = 0.f;
    for (int e = start; e < end; e++) {
        int s = g_col[e];
        float ns = g_dinv[s];
        const float* hp = &g_h2[(size_t)s * D_OUT];
        acc0 = fmaf(ns, hp[lane], acc0);
        if (hi) acc1 = fmaf(ns, hp[lane + 32], acc1);
    }
    float di = g_dinv[node];
    const float* sp = &g_h2[(size_t)node * D_OUT];
    float v0 = fmaf(di, fmaf(di, sp[lane], acc0), b2[lane]);
    float v1 = 0.f;
    if (hi) v1 = fmaf(di, fmaf(di, sp[lane + 32], acc1), b2[lane + 32]);

    float m = hi ? fmaxf(v0, v1) : v0;
    #pragma unroll
    for (int o = 16; o >= 1; o >>= 1)
        m = fmaxf(m, __shfl_xor_sync(0xffffffffu, m, o));
    float s = expf(v0 - m) + (hi ? expf(v1 - m) : 0.f);
    #pragma unroll
    for (int o = 16; o >= 1; o >>= 1)
        s += __shfl_xor_sync(0xffffffffu, s, o);
    float ls = logf(s);

    out[node * D_OUT + lane] = v0 - m - ls;
    if (hi) out[node * D_OUT + 32 + lane] = v1 - m - ls;
}

// ---------------- launch --------------------------------------------------------
extern "C" void kernel_launch(void* const* d_in, const int* in_sizes, int n_in,
                              void* d_out, int out_size) {
    const float* x   = (const float*)d_in[0];
    const int*   ei  = (const int*)d_in[1];    // edge_index is int32 (JAX x64 disabled)
    const float* W1  = (const float*)d_in[2];
    const float* b1  = (const float*)d_in[3];
    const float* W2  = (const float*)d_in[4];
    const float* b2  = (const float*)d_in[5];
    float* out = (float*)d_out;

    const int n = in_sizes[0] / D_IN;   // 100000
    const int e = in_sizes[1] / 2;      // 1600000
    const int* src = ei;
    const int* dst = ei + e;

    const int nb_scan = (n + SCAN_B - 1) / SCAN_B;

    zero_cnt_kernel<<<(n + 255) / 256, 256>>>(n);
    count_kernel<<<(e + 255) / 256, 256>>>(dst, e);
    scan_block_kernel<<<nb_scan, SCAN_B>>>(n);
    scan_partials_kernel<<<1, 512>>>(nb_scan);
    scan_add_kernel<<<nb_scan, SCAN_B>>>(n, e);
    fill_csr_kernel<<<(e + 255) / 256, 256>>>(src, dst, e);

    w1_prep_kernel<<<(D_IN * D_H + 255) / 256, 256>>>(W1);
    w2_prep_kernel<<<(128 * 28 + 255) / 256, 256>>>(W2);
    gemm1_mma_kernel<<<(n + 127) / 128, 256>>>(x, n);
    agg1_kernel<<<(n * 32 + 255) / 256, 256>>>(b1, n);
    gemm2_mma_kernel<<<(n + 127) / 128, 256>>>(n);
    agg2_kernel<<<(n * 32 + 255) / 256, 256>>>(b2, out, n);
}

// round 7
// speedup vs baseline: 2.0122x; 1.0339x over previous
#include <cuda_runtime.h>
#include <cuda_bf16.h>
#include <math.h>
#include <stdint.h>

#define NMAX 100000
#define EMAX 1600000
#define D_IN 512
#define D_H  128
#define D_OUT 40
#define SCAN_B 512

// ================= scratch (static device globals; no dynamic alloc) ===========
__device__ int      g_cnt[NMAX];
__device__ int      g_local[NMAX];
__device__ int      g_partials[512];
__device__ int      g_row_ptr[NMAX + 1];
__device__ int      g_cursor[NMAX];
__device__ int      g_col[EMAX];
__device__ float    g_dinv[NMAX];
__device__ float    g_h1 [NMAX * D_H];
__device__ float    g_h2 [NMAX * D_OUT];
// h1a (post agg+relu) stored pre-split as bf16 hi/lo, packed 2 per u32, row = 64 u32
__device__ uint32_t g_h1h[NMAX * 64];
__device__ uint32_t g_h1l[NMAX * 64];
// W1 split into bf16 hi/lo, [k=512][n=128] row-major (bit patterns as ushort)
__device__ uint16_t g_w1h[D_IN * D_H];
__device__ uint16_t g_w1l[D_IN * D_H];
// W2 split into bf16 hi/lo, [k=128][n=56 padded] stored as u32 words [128][28]
__device__ uint32_t g_w2h[128 * 28];
__device__ uint32_t g_w2l[128 * 28];

// ================= small helpers ================================================
__device__ __forceinline__ uint32_t smem_u32(const void* p) {
    uint32_t a;
    asm("{ .reg .u64 t; cvta.to.shared.u64 t, %1; cvt.u32.u64 %0, t; }" : "=r"(a) : "l"(p));
    return a;
}

__device__ __forceinline__ uint16_t bf16_bits(float v) {
    __nv_bfloat16 h = __float2bfloat16(v);
    return *reinterpret_cast<uint16_t*>(&h);
}
__device__ __forceinline__ float bf16_val(uint16_t b) {
    __nv_bfloat16 h = *reinterpret_cast<__nv_bfloat16*>(&b);
    return __bfloat162float(h);
}

// ldmatrix x4 (A, row-major 16x16 bf16 tile, row stride 40 bf16)
__device__ __forceinline__ void ldmA(uint32_t* d, const uint16_t* sm, int m0, int kk, int lane) {
    uint32_t addr = smem_u32(sm + (m0 + (lane & 15)) * 40 + kk + ((lane >> 4) << 3));
    asm volatile("ldmatrix.sync.aligned.m8n8.x4.shared.b16 {%0,%1,%2,%3}, [%4];"
                 : "=r"(d[0]), "=r"(d[1]), "=r"(d[2]), "=r"(d[3]) : "r"(addr) : "memory");
}

// ldmatrix x4 trans (B, [k][n] row-major stride 136; two n8 tiles)
__device__ __forceinline__ void ldmB(uint32_t* d, const uint16_t* sm, int kk, int n0, int lane) {
    uint32_t addr = smem_u32(sm + (kk + (lane & 15)) * 136 + n0 + ((lane >> 4) << 3));
    asm volatile("ldmatrix.sync.aligned.m8n8.x4.trans.shared.b16 {%0,%1,%2,%3}, [%4];"
                 : "=r"(d[0]), "=r"(d[1]), "=r"(d[2]), "=r"(d[3]) : "r"(addr) : "memory");
}

// ldmatrix x2 trans (B, [k][n] row-major stride 56; one n8 tile, k16)
__device__ __forceinline__ void ldmB2(uint32_t* d, const uint16_t* sm, int kk, int n0, int lane) {
    uint32_t addr = smem_u32(sm + (kk + (lane & 15)) * 56 + n0);
    asm volatile("ldmatrix.sync.aligned.m8n8.x2.trans.shared.b16 {%0,%1}, [%2];"
                 : "=r"(d[0]), "=r"(d[1]) : "r"(addr) : "memory");
}

__device__ __forceinline__ void mma_bf16(float* c, const uint32_t* a, const uint32_t* b) {
    asm volatile("mma.sync.aligned.m16n8k16.row.col.f32.bf16.bf16.f32 "
                 "{%0,%1,%2,%3}, {%4,%5,%6,%7}, {%8,%9}, {%0,%1,%2,%3};"
                 : "+f"(c[0]), "+f"(c[1]), "+f"(c[2]), "+f"(c[3])
                 : "r"(a[0]), "r"(a[1]), "r"(a[2]), "r"(a[3]), "r"(b[0]), "r"(b[1]));
}

// ---------------- degree / CSR build -------------------------------------------
__global__ void zero_cnt_kernel(int n) {
    int i = blockIdx.x * blockDim.x + threadIdx.x;
    if (i < n) g_cnt[i] = 0;
}

__global__ void count_kernel(const int* __restrict__ dst, int e_cnt) {
    int e = blockIdx.x * blockDim.x + threadIdx.x;
    if (e < e_cnt) atomicAdd(&g_cnt[dst[e]], 1);
}

__global__ void scan_block_kernel(int n) {
    __shared__ int sh[SCAN_B];
    int i = blockIdx.x * SCAN_B + threadIdx.x;
    int v = (i < n) ? g_cnt[i] : 0;
    sh[threadIdx.x] = v;
    __syncthreads();
    #pragma unroll
    for (int off = 1; off < SCAN_B; off <<= 1) {
        int t = 0;
        if ((int)threadIdx.x >= off) t = sh[threadIdx.x - off];
        __syncthreads();
        sh[threadIdx.x] += t;
        __syncthreads();
    }
    if (i < n) g_local[i] = sh[threadIdx.x] - v;
    if (threadIdx.x == SCAN_B - 1) g_partials[blockIdx.x] = sh[SCAN_B - 1];
}

__global__ void scan_partials_kernel(int nb) {
    __shared__ int sh[512];
    int t = threadIdx.x;
    int v = (t < nb) ? g_partials[t] : 0;
    sh[t] = v;
    __syncthreads();
    #pragma unroll
    for (int off = 1; off < 512; off <<= 1) {
        int tv = 0;
        if (t >= off) tv = sh[t - off];
        __syncthreads();
        sh[t] += tv;
        __syncthreads();
    }
    if (t < nb) g_partials[t] = sh[t] - v;
}

__global__ void scan_add_kernel(int n, int e_cnt) {
    int i = blockIdx.x * SCAN_B + threadIdx.x;
    if (i < n) {
        int r = g_local[i] + g_partials[blockIdx.x];
        g_row_ptr[i] = r;
        g_cursor[i]  = r;
        g_dinv[i] = rsqrtf((float)(g_cnt[i] + 1));
    }
    if (i == 0) g_row_ptr[n] = e_cnt;
}

__global__ void fill_csr_kernel(const int* __restrict__ src,
                                const int* __restrict__ dst, int e_cnt) {
    int e = blockIdx.x * blockDim.x + threadIdx.x;
    if (e < e_cnt) {
        int d = dst[e];
        int pos = atomicAdd(&g_cursor[d], 1);
        g_col[pos] = src[e];
    }
}

// ---------------- weight prep ----------------------------------------------------
__global__ void w1_prep_kernel(const float* __restrict__ W1) {
    int i = blockIdx.x * blockDim.x + threadIdx.x;
    if (i >= D_IN * D_H) return;
    float v = W1[i];
    uint16_t h = bf16_bits(v);
    g_w1h[i] = h;
    g_w1l[i] = bf16_bits(v - bf16_val(h));
}

// W2 [128][40] fp32 -> padded [128][56] bf16 hi/lo as u32 words [128][28]
__global__ void w2_prep_kernel(const float* __restrict__ W2) {
    int i = blockIdx.x * blockDim.x + threadIdx.x;
    if (i >= 128 * 28) return;
    int k = i / 28;
    int j = i % 28;
    float v0 = (2 * j     < D_OUT) ? W2[k * D_OUT + 2 * j]     : 0.f;
    float v1 = (2 * j + 1 < D_OUT) ? W2[k * D_OUT + 2 * j + 1] : 0.f;
    uint16_t h0 = bf16_bits(v0), h1 = bf16_bits(v1);
    uint16_t l0 = bf16_bits(v0 - bf16_val(h0)), l1 = bf16_bits(v1 - bf16_val(h1));
    g_w2h[i] = (uint32_t)h0 | ((uint32_t)h1 << 16);
    g_w2l[i] = (uint32_t)l0 | ((uint32_t)l1 << 16);
}

// ---------------- GEMM1 (HMMA): h1 = x @ W1  (M x 512) @ (512 x 128) -----------
__global__ __launch_bounds__(256, 2) void gemm1_mma_kernel(const float* __restrict__ A, int M) {
    __shared__ __align__(16) uint16_t As_hi[128 * 40];
    __shared__ __align__(16) uint16_t As_lo[128 * 40];
    __shared__ __align__(16) uint16_t Bs_hi[32 * 136];
    __shared__ __align__(16) uint16_t Bs_lo[32 * 136];

    const int tid  = threadIdx.x;
    const int lane = tid & 31;
    const int wid  = tid >> 5;
    const int wm   = wid >> 1;
    const int wn   = wid & 1;
    const int row0 = blockIdx.x * 128;

    int am[4], akq[4];
    bool aok[4];
    #pragma unroll
    for (int i = 0; i < 4; i++) {
        int idx = tid + i * 256;
        am[i]  = idx >> 3;
        akq[i] = idx & 7;
        aok[i] = (row0 + am[i]) < M;
    }

    float acc[2][8][4];
    #pragma unroll
    for (int a = 0; a < 2; a++)
        #pragma unroll
        for (int b = 0; b < 8; b++)
            #pragma unroll
            for (int c = 0; c < 4; c++) acc[a][b][c] = 0.f;

    uint32_t* Ah32 = reinterpret_cast<uint32_t*>(As_hi);
    uint32_t* Al32 = reinterpret_cast<uint32_t*>(As_lo);

    float4 v[4];
    #pragma unroll
    for (int i = 0; i < 4; i++)
        v[i] = aok[i] ? *(const float4*)&A[(size_t)(row0 + am[i]) * D_IN + akq[i] * 4]
                      : make_float4(0.f, 0.f, 0.f, 0.f);

    for (int ch = 0; ch < 16; ch++) {
        #pragma unroll
        for (int i = 0; i < 4; i++) {
            uint16_t h0 = bf16_bits(v[i].x), h1 = bf16_bits(v[i].y),
                     h2 = bf16_bits(v[i].z), h3 = bf16_bits(v[i].w);
            uint16_t l0 = bf16_bits(v[i].x - bf16_val(h0)), l1 = bf16_bits(v[i].y - bf16_val(h1)),
                     l2 = bf16_bits(v[i].z - bf16_val(h2)), l3 = bf16_bits(v[i].w - bf16_val(h3));
            int w = am[i] * 20 + akq[i] * 2;
            Ah32[w]     = (uint32_t)h0 | ((uint32_t)h1 << 16);
            Ah32[w + 1] = (uint32_t)h2 | ((uint32_t)h3 << 16);
            Al32[w]     = (uint32_t)l0 | ((uint32_t)l1 << 16);
            Al32[w + 1] = (uint32_t)l2 | ((uint32_t)l3 << 16);
        }
        const int k0 = ch * 32;
        #pragma unroll
        for (int i = 0; i < 2; i++) {
            int idx = tid + i * 256;
            int k = idx >> 4;
            int u = idx & 15;
            *(uint4*)&Bs_hi[k * 136 + u * 8] = *(const uint4*)&g_w1h[(size_t)(k0 + k) * D_H + u * 8];
            *(uint4*)&Bs_lo[k * 136 + u * 8] = *(const uint4*)&g_w1l[(size_t)(k0 + k) * D_H + u * 8];
        }
        __syncthreads();

        if (ch < 15) {
            const int kn = (ch + 1) * 32;
            #pragma unroll
            for (int i = 0; i < 4; i++)
                v[i] = aok[i] ? *(const float4*)&A[(size_t)(row0 + am[i]) * D_IN + kn + akq[i] * 4]
                              : make_float4(0.f, 0.f, 0.f, 0.f);
        }

        #pragma unroll
        for (int kk = 0; kk < 32; kk += 16) {
            uint32_t ah[2][4], al[2][4];
            #pragma unroll
            for (int mt = 0; mt < 2; mt++) {
                ldmA(ah[mt], As_hi, wm * 32 + mt * 16, kk, lane);
                ldmA(al[mt], As_lo, wm * 32 + mt * 16, kk, lane);
            }
            #pragma unroll
            for (int ng = 0; ng < 4; ng++) {
                uint32_t bh[4], bl[4];
                ldmB(bh, Bs_hi, kk, wn * 64 + ng * 16, lane);
                ldmB(bl, Bs_lo, kk, wn * 64 + ng * 16, lane);
                #pragma unroll
                for (int mt = 0; mt < 2; mt++) {
                    mma_bf16(acc[mt][ng * 2],     ah[mt], bh);
                    mma_bf16(acc[mt][ng * 2],     ah[mt], bl);
                    mma_bf16(acc[mt][ng * 2],     al[mt], bh);
                    mma_bf16(acc[mt][ng * 2 + 1], ah[mt], bh + 2);
                    mma_bf16(acc[mt][ng * 2 + 1], ah[mt], bl + 2);
                    mma_bf16(acc[mt][ng * 2 + 1], al[mt], bh + 2);
                }
            }
        }
        __syncthreads();
    }

    const int g  = lane >> 2;
    const int tg = lane & 3;
    #pragma unroll
    for (int mt = 0; mt < 2; mt++) {
        #pragma unroll
        for (int nt = 0; nt < 8; nt++) {
            int col = wn * 64 + nt * 8 + tg * 2;
            int r0  = row0 + wm * 32 + mt * 16 + g;
            if (r0 < M)
                *(float2*)&g_h1[(size_t)r0 * D_H + col] =
                    make_float2(acc[mt][nt][0], acc[mt][nt][1]);
            int r1 = r0 + 8;
            if (r1 < M)
                *(float2*)&g_h1[(size_t)r1 * D_H + col] =
                    make_float2(acc[mt][nt][2], acc[mt][nt][3]);
        }
    }
}

// ---------------- Aggregation layer 1: warp per node, MLP-4 unroll -------------
__global__ void agg1_kernel(const float* __restrict__ b1, int n) {
    int warp = (blockIdx.x * blockDim.x + threadIdx.x) >> 5;
    int lane = threadIdx.x & 31;
    if (warp >= n) return;
    const int node = warp;
    const int start = g_row_ptr[node];
    const int end   = g_row_ptr[node + 1];
    const int co = lane << 2;

    float4 a0 = make_float4(0.f,0.f,0.f,0.f), a1 = a0, a2 = a0, a3 = a0;
    int e = start;
    for (; e + 4 <= end; e += 4) {
        int s0 = g_col[e], s1 = g_col[e+1], s2 = g_col[e+2], s3 = g_col[e+3];
        float d0 = g_dinv[s0], d1 = g_dinv[s1], d2 = g_dinv[s2], d3 = g_dinv[s3];
        float4 v0 = *(const float4*)&g_h1[(size_t)s0 * D_H + co];
        float4 v1 = *(const float4*)&g_h1[(size_t)s1 * D_H + co];
        float4 v2 = *(const float4*)&g_h1[(size_t)s2 * D_H + co];
        float4 v3 = *(const float4*)&g_h1[(size_t)s3 * D_H + co];
        a0.x = fmaf(d0, v0.x, a0.x); a0.y = fmaf(d0, v0.y, a0.y);
        a0.z = fmaf(d0, v0.z, a0.z); a0.w = fmaf(d0, v0.w, a0.w);
        a1.x = fmaf(d1, v1.x, a1.x); a1.y = fmaf(d1, v1.y, a1.y);
        a1.z = fmaf(d1, v1.z, a1.z); a1.w = fmaf(d1, v1.w, a1.w);
        a2.x = fmaf(d2, v2.x, a2.x); a2.y = fmaf(d2, v2.y, a2.y);
        a2.z = fmaf(d2, v2.z, a2.z); a2.w = fmaf(d2, v2.w, a2.w);
        a3.x = fmaf(d3, v3.x, a3.x); a3.y = fmaf(d3, v3.y, a3.y);
        a3.z = fmaf(d3, v3.z, a3.z); a3.w = fmaf(d3, v3.w, a3.w);
    }
    for (; e < end; e++) {
        int s = g_col[e];
        float d = g_dinv[s];
        float4 vv = *(const float4*)&g_h1[(size_t)s * D_H + co];
        a0.x = fmaf(d, vv.x, a0.x); a0.y = fmaf(d, vv.y, a0.y);
        a0.z = fmaf(d, vv.z, a0.z); a0.w = fmaf(d, vv.w, a0.w);
    }
    float4 acc;
    acc.x = (a0.x + a1.x) + (a2.x + a3.x);
    acc.y = (a0.y + a1.y) + (a2.y + a3.y);
    acc.z = (a0.z + a1.z) + (a2.z + a3.z);
    acc.w = (a0.w + a1.w) + (a2.w + a3.w);

    float di = g_dinv[node];
    float4 sv = *(const float4*)&g_h1[(size_t)node * D_H + co];
    float4 bb = *(const float4*)&b1[co];
    float4 o;
    o.x = fmaxf(fmaf(di, fmaf(di, sv.x, acc.x), bb.x), 0.f);
    o.y = fmaxf(fmaf(di, fmaf(di, sv.y, acc.y), bb.y), 0.f);
    o.z = fmaxf(fmaf(di, fmaf(di, sv.z, acc.z), bb.z), 0.f);
    o.w = fmaxf(fmaf(di, fmaf(di, sv.w, acc.w), bb.w), 0.f);

    uint16_t h0 = bf16_bits(o.x), h1 = bf16_bits(o.y), h2 = bf16_bits(o.z), h3 = bf16_bits(o.w);
    uint16_t l0 = bf16_bits(o.x - bf16_val(h0)), l1 = bf16_bits(o.y - bf16_val(h1)),
             l2 = bf16_bits(o.z - bf16_val(h2)), l3 = bf16_bits(o.w - bf16_val(h3));
    uint2 hp = make_uint2((uint32_t)h0 | ((uint32_t)h1 << 16), (uint32_t)h2 | ((uint32_t)h3 << 16));
    uint2 lp = make_uint2((uint32_t)l0 | ((uint32_t)l1 << 16), (uint32_t)l2 | ((uint32_t)l3 << 16));
    *(uint2*)&g_h1h[(size_t)node * 64 + lane * 2] = hp;
    *(uint2*)&g_h1l[(size_t)node * 64 + lane * 2] = lp;
}

// ---------------- GEMM2 (HMMA): h2 = h1a @ W2  (M x 128) @ (128 x 40) ----------
__global__ __launch_bounds__(256) void gemm2_mma_kernel(int M) {
    __shared__ __align__(16) uint16_t Ah[128 * 40];
    __shared__ __align__(16) uint16_t Al[128 * 40];
    __shared__ __align__(16) uint16_t Bh[32 * 56];
    __shared__ __align__(16) uint16_t Bl[32 * 56];

    const int tid  = threadIdx.x;
    const int lane = tid & 31;
    const int wid  = tid >> 5;
    const int row0 = blockIdx.x * 128;

    uint32_t* Ah32 = reinterpret_cast<uint32_t*>(Ah);
    uint32_t* Al32 = reinterpret_cast<uint32_t*>(Al);
    uint32_t* Bh32 = reinterpret_cast<uint32_t*>(Bh);
    uint32_t* Bl32 = reinterpret_cast<uint32_t*>(Bl);

    float acc[5][4];
    #pragma unroll
    for (int a = 0; a < 5; a++)
        #pragma unroll
        for (int c = 0; c < 4; c++) acc[a][c] = 0.f;

    for (int ch = 0; ch < 4; ch++) {
        const int kw0 = ch * 16;
        #pragma unroll
        for (int i = 0; i < 8; i++) {
            int idx = tid + i * 256;
            int m = idx >> 4, j = idx & 15;
            int r = row0 + m;
            uint32_t vh = 0, vl = 0;
            if (r < M) {
                vh = g_h1h[(size_t)r * 64 + kw0 + j];
                vl = g_h1l[(size_t)r * 64 + kw0 + j];
            }
            Ah32[m * 20 + j] = vh;
            Al32[m * 20 + j] = vl;
        }
        #pragma unroll
        for (int i = 0; i < 4; i++) {
            int idx = tid + i * 256;
            if (idx < 896) {
                int k = idx / 28, j = idx % 28;
                Bh32[k * 28 + j] = g_w2h[(ch * 32 + k) * 28 + j];
                Bl32[k * 28 + j] = g_w2l[(ch * 32 + k) * 28 + j];
            }
        }
        __syncthreads();

        #pragma unroll
        for (int kk = 0; kk < 32; kk += 16) {
            uint32_t ah[4], al[4];
            ldmA(ah, Ah, wid * 16, kk, lane);
            ldmA(al, Al, wid * 16, kk, lane);
            #pragma unroll
            for (int nt = 0; nt < 5; nt++) {
                uint32_t bh[2], bl[2];
                ldmB2(bh, Bh, kk, nt * 8, lane);
                ldmB2(bl, Bl, kk, nt * 8, lane);
                mma_bf16(acc[nt], ah, bh);
                mma_bf16(acc[nt], ah, bl);
                mma_bf16(acc[nt], al, bh);
            }
        }
        __syncthreads();
    }

    const int g  = lane >> 2;
    const int tg = lane & 3;
    #pragma unroll
    for (int nt = 0; nt < 5; nt++) {
        int col = nt * 8 + tg * 2;
        int r0  = row0 + wid * 16 + g;
        if (r0 < M)
            *(float2*)&g_h2[(size_t)r0 * D_OUT + col] = make_float2(acc[nt][0], acc[nt][1]);
        int r1 = r0 + 8;
        if (r1 < M)
            *(float2*)&g_h2[(size_t)r1 * D_OUT + col] = make_float2(acc[nt][2], acc[nt][3]);
    }
}

// ---------------- Aggregation layer 2 + bias + log_softmax (MLP-4) -------------
__global__ void agg2_kernel(const float* __restrict__ b2, float* __restrict__ out, int n) {
    int warp = (blockIdx.x * blockDim.x + threadIdx.x) >> 5;
    int lane = threadIdx.x & 31;
    if (warp >= n) return;
    const int node = warp;
    const int start = g_row_ptr[node];
    const int end   = g_row_ptr[node + 1];
    const bool hi = (lane < 8);

    float p0 = 0.f, p1 = 0.f, p2 = 0.f, p3 = 0.f;
    float q0 = 0.f, q1 = 0.f, q2 = 0.f, q3 = 0.f;
    int e = start;
    for (; e + 4 <= end; e += 4) {
        int s0 = g_col[e], s1 = g_col[e+1], s2 = g_col[e+2], s3 = g_col[e+3];
        float d0 = g_dinv[s0], d1 = g_dinv[s1], d2 = g_dinv[s2], d3 = g_dinv[s3];
        const float* h0p = &g_h2[(size_t)s0 * D_OUT];
        const float* h1p = &g_h2[(size_t)s1 * D_OUT];
        const float* h2p = &g_h2[(size_t)s2 * D_OUT];
        const float* h3p = &g_h2[(size_t)s3 * D_OUT];
        float x0 = h0p[lane], x1 = h1p[lane], x2 = h2p[lane], x3 = h3p[lane];
        p0 = fmaf(d0, x0, p0); p1 = fmaf(d1, x1, p1);
        p2 = fmaf(d2, x2, p2); p3 = fmaf(d3, x3, p3);
        if (hi) {
            float y0 = h0p[lane + 32], y1 = h1p[lane + 32],
                  y2 = h2p[lane + 32], y3 = h3p[lane + 32];
            q0 = fmaf(d0, y0, q0); q1 = fmaf(d1, y1, q1);
            q2 = fmaf(d2, y2, q2); q3 = fmaf(d3, y3, q3);
        }
    }
    for (; e < end; e++) {
        int s = g_col[e];
        float d = g_dinv[s];
        const float* hp = &g_h2[(size_t)s * D_OUT];
        p0 = fmaf(d, hp[lane], p0);
        if (hi) q0 = fmaf(d, hp[lane + 32], q0);
    }
    float acc0 = (p0 + p1) + (p2 + p3);
    float acc1 = (q0 + q1) + (q2 + q3);

    float di = g_dinv[node];
    const float* sp = &g_h2[(size_t)node * D_OUT];
    float v0 = fmaf(di, fmaf(di, sp[lane], acc0), b2[lane]);
    float v1 = 0.f;
    if (hi) v1 = fmaf(di, fmaf(di, sp[lane + 32], acc1), b2[lane + 32]);

    float m = hi ? fmaxf(v0, v1) : v0;
    #pragma unroll
    for (int o = 16; o >= 1; o >>= 1)
        m = fmaxf(m, __shfl_xor_sync(0xffffffffu, m, o));
    float s = expf(v0 - m) + (hi ? expf(v1 - m) : 0.f);
    #pragma unroll
    for (int o = 16; o >= 1; o >>= 1)
        s += __shfl_xor_sync(0xffffffffu, s, o);
    float ls = logf(s);

    out[node * D_OUT + lane] = v0 - m - ls;
    if (hi) out[node * D_OUT + 32 + lane] = v1 - m - ls;
}

// ---------------- launch --------------------------------------------------------
extern "C" void kernel_launch(void* const* d_in, const int* in_sizes, int n_in,
                              void* d_out, int out_size) {
    const float* x   = (const float*)d_in[0];
    const int*   ei  = (const int*)d_in[1];    // edge_index is int32 (JAX x64 disabled)
    const float* W1  = (const float*)d_in[2];
    const float* b1  = (const float*)d_in[3];
    const float* W2  = (const float*)d_in[4];
    const float* b2  = (const float*)d_in[5];
    float* out = (float*)d_out;

    const int n = in_sizes[0] / D_IN;   // 100000
    const int e = in_sizes[1] / 2;      // 1600000
    const int* src = ei;
    const int* dst = ei + e;

    const int nb_scan = (n + SCAN_B - 1) / SCAN_B;

    // one-time side-stream + events for fork/join inside graph capture
    static cudaStream_t s_csr = nullptr;
    static cudaEvent_t ev_fork = nullptr, ev_join = nullptr;
    if (s_csr == nullptr) {
        cudaStreamCreateWithFlags(&s_csr, cudaStreamNonBlocking);
        cudaEventCreateWithFlags(&ev_fork, cudaEventDisableTiming);
        cudaEventCreateWithFlags(&ev_join, cudaEventDisableTiming);
    }

    // ---- fork: CSR build on side stream, GEMM path on main stream ----
    cudaEventRecord(ev_fork, 0);
    cudaStreamWaitEvent(s_csr, ev_fork, 0);

    zero_cnt_kernel<<<(n + 255) / 256, 256, 0, s_csr>>>(n);
    count_kernel<<<(e + 255) / 256, 256, 0, s_csr>>>(dst, e);
    scan_block_kernel<<<nb_scan, SCAN_B, 0, s_csr>>>(n);
    scan_partials_kernel<<<1, 512, 0, s_csr>>>(nb_scan);
    scan_add_kernel<<<nb_scan, SCAN_B, 0, s_csr>>>(n, e);
    fill_csr_kernel<<<(e + 255) / 256, 256, 0, s_csr>>>(src, dst, e);
    cudaEventRecord(ev_join, s_csr);

    w1_prep_kernel<<<(D_IN * D_H + 255) / 256, 256>>>(W1);
    w2_prep_kernel<<<(128 * 28 + 255) / 256, 256>>>(W2);
    gemm1_mma_kernel<<<(n + 127) / 128, 256>>>(x, n);

    // ---- join: aggregation needs both CSR and h1 ----
    cudaStreamWaitEvent(0, ev_join, 0);

    agg1_kernel<<<(n * 32 + 255) / 256, 256>>>(b1, n);
    gemm2_mma_kernel<<<(n + 127) / 128, 256>>>(n);
    agg2_kernel<<<(n * 32 + 255) / 256, 256>>>(b2, out, n);
}